// round 4
// baseline (speedup 1.0000x reference)
#include <cuda_runtime.h>
#include <cstdint>
#include <math.h>

#define BB   256
#define SS   4096
#define VV   6
#define DD   32
#define HH   16
#define PADV 5
#define KK   614          // max(1, int(4096*0.15))
#define CL   4            // chunks per row
#define TPB  256
#define TOKC (SS / CL)    // 1024 tokens per chunk
#define NW   (TPB / 32)

// Cross-kernel scratch
__device__ int   g_counts[BB][CL][VV];
__device__ float g_sscore[VV];
__device__ float g_arow[VV][DD];
__device__ int   g_order[VV];

// ---------------- K1: per-chunk vocab counts (half-row CTAs) + one MLP CTA ----------------
__global__ __launch_bounds__(TPB, 8) void count_kernel(
    const int*   __restrict__ x,
    const float* __restrict__ emb,
    const float* __restrict__ sw1, const float* __restrict__ sb1,
    const float* __restrict__ sw2, const float* __restrict__ sb2,
    const float* __restrict__ aw1, const float* __restrict__ ab1,
    const float* __restrict__ aw2, const float* __restrict__ ab2)
{
    const int t = threadIdx.x;

    if (blockIdx.x < BB * 2) {
        // CTA covers half a row (2048 tokens); warp w covers 256 contiguous tokens.
        const int b    = blockIdx.x >> 1;
        const int half = blockIdx.x & 1;
        const int lane = t & 31;
        const int warp = t >> 5;
        const int4* base = (const int4*)(x + (size_t)b * SS + half * (SS / 2));

        const int4 a0 = base[warp * 64 + lane];
        const int4 a1 = base[warp * 64 + 32 + lane];

        unsigned long long cpack =
            (1ull << (10 * a0.x)) + (1ull << (10 * a0.y)) +
            (1ull << (10 * a0.z)) + (1ull << (10 * a0.w)) +
            (1ull << (10 * a1.x)) + (1ull << (10 * a1.y)) +
            (1ull << (10 * a1.z)) + (1ull << (10 * a1.w));
        #pragma unroll
        for (int off = 16; off > 0; off >>= 1)
            cpack += __shfl_xor_sync(0xffffffffu, cpack, off);

        __shared__ unsigned long long wtot[NW];
        if (lane == 0) wtot[warp] = cpack;
        __syncthreads();
        // warps 0-3 -> chunk 2*half, warps 4-7 -> chunk 2*half+1
        if (t < VV) {
            int s = 0;
            #pragma unroll
            for (int w = 0; w < 4; ++w) s += (int)((wtot[w] >> (10 * t)) & 1023ull);
            g_counts[b][2 * half][t] = s;
        } else if (t >= 32 && t < 32 + VV) {
            int v = t - 32, s = 0;
            #pragma unroll
            for (int w = 4; w < 8; ++w) s += (int)((wtot[w] >> (10 * v)) & 1023ull);
            g_counts[b][2 * half + 1][v] = s;
        }
        return;
    }

    // ---- single MLP CTA: vocab-level tables (row-independent) ----
    __shared__ float table[VV][DD];
    __shared__ float rbuf[VV][DD];
    __shared__ float hbuf[VV][HH];
    __shared__ float ssc[VV];

    if (t < VV * DD) {
        int v = t >> 5, i = t & 31;
        table[v][i] = (v == PADV) ? 0.0f : emb[v * DD + i];
    }
    __syncthreads();
    if (t < VV * DD) {
        int v = t >> 5, i = t & 31;
        float acc = ab1[i];
        #pragma unroll
        for (int d = 0; d < DD; ++d) acc += table[v][d] * aw1[d * DD + i];
        rbuf[v][i] = fmaxf(acc, 0.0f);
    }
    if (t < VV * HH) {
        int v = t >> 4, j = t & 15;
        float acc = sb1[j];
        #pragma unroll
        for (int d = 0; d < DD; ++d) acc += table[v][d] * sw1[d * HH + j];
        hbuf[v][j] = fmaxf(acc, 0.0f);
    }
    __syncthreads();
    if (t < VV * DD) {
        int v = t >> 5, i = t & 31;
        float acc = ab2[i];
        #pragma unroll
        for (int m = 0; m < DD; ++m) acc += rbuf[v][m] * aw2[m * DD + i];
        g_arow[v][i] = acc;
    }
    if (t >= 224 && t < 224 + VV) {
        int v = t - 224;
        float acc = sb2[0];
        #pragma unroll
        for (int j = 0; j < HH; ++j) acc += hbuf[v][j] * sw2[j];
        float s = 1.0f / (1.0f + expf(-acc));
        ssc[v] = s;
        g_sscore[v] = s;
    }
    __syncthreads();
    if (t == 0) {
        int order[VV];
        #pragma unroll
        for (int v = 0; v < VV; ++v) order[v] = v;
        for (int a = 0; a < VV; ++a) {
            int best = a;
            for (int q = a + 1; q < VV; ++q)
                if (ssc[order[q]] > ssc[order[best]]) best = q;
            int tmp = order[a]; order[a] = order[best]; order[best] = tmp;
        }
        #pragma unroll
        for (int a = 0; a < VV; ++a) g_order[a] = order[a];
    }
}

// ---------------- K2: scores + top_idx + pred ----------------
__global__ __launch_bounds__(TPB, 8) void emit_kernel(
    const int*   __restrict__ x,
    const float* __restrict__ cw1, const float* __restrict__ cb1,
    const float* __restrict__ cw2, const float* __restrict__ cb2,
    float* __restrict__ out_pred,
    float* __restrict__ out_top,
    float* __restrict__ out_sc)
{
    __shared__ float sscore[VV];
    __shared__ int   allc[CL][VV];
    __shared__ int   order_sh[VV];
    __shared__ int   warpsum[NW][VV];
    __shared__ int   take[VV], obase[VV], cpre_sh[VV];
    __shared__ float pooled[DD];
    __shared__ float h2[HH];

    const int t    = threadIdx.x;
    const int lane = t & 31;
    const int warp = t >> 5;
    const int b    = blockIdx.x >> 2;
    const int c    = blockIdx.x & 3;

    const int4 xw = ((const int4*)(x + (size_t)b * SS + c * TOKC))[t];

    if (t < VV)                 sscore[t] = g_sscore[t];
    if (t >= 32 && t < 32 + VV) order_sh[t - 32] = g_order[t - 32];
    if (t >= 64 && t < 64 + CL * VV) {
        int i = t - 64;
        allc[i / VV][i % VV] = g_counts[b][i / VV][i % VV];
    }

    // packed per-thread counts + warp inclusive scan (stability: ascending position)
    unsigned long long cpack =
        (1ull << (10 * xw.x)) + (1ull << (10 * xw.y)) +
        (1ull << (10 * xw.z)) + (1ull << (10 * xw.w));
    const unsigned long long own = cpack;
    #pragma unroll
    for (int off = 1; off < 32; off <<= 1) {
        unsigned long long n = __shfl_up_sync(0xffffffffu, cpack, off);
        if (lane >= off) cpack += n;
    }
    if (lane == 31) {
        #pragma unroll
        for (int v = 0; v < VV; ++v)
            warpsum[warp][v] = (int)((cpack >> (10 * v)) & 1023ull);
    }
    __syncthreads();                                           // S1

    if (t < VV) {
        int run = 0;
        #pragma unroll
        for (int w = 0; w < NW; ++w) { int s = warpsum[w][t]; warpsum[w][t] = run; run += s; }
        int pre = 0;
        #pragma unroll
        for (int r = 0; r < CL; ++r) if (r < c) pre += allc[r][t];
        cpre_sh[t] = pre;
    }
    if (t == 32) {
        int budget = KK, off = 0;
        #pragma unroll
        for (int r = 0; r < VV; ++r) {
            int v = order_sh[r];
            int tot = allc[0][v] + allc[1][v] + allc[2][v] + allc[3][v];
            int tk  = min(tot, budget);
            take[v]  = tk;
            obase[v] = off;
            off    += tk;
            budget -= tk;
        }
    }
    // scores output (valid after S1)
    {
        float4 f;
        f.x = sscore[xw.x]; f.y = sscore[xw.y];
        f.z = sscore[xw.z]; f.w = sscore[xw.w];
        ((float4*)(out_sc + (size_t)b * SS + c * TOKC))[t] = f;
    }
    __syncthreads();                                           // S2

    // top_idx emit: STATIC per-vocab loop, no dynamically-indexed register arrays
    {
        const unsigned long long excl = cpack - own;
        float* trow = out_top + (size_t)b * KK;
        const int pbase = c * TOKC + t * 4;
        #pragma unroll
        for (int v = 0; v < VV; ++v) {
            int ord = cpre_sh[v] + warpsum[warp][v] + (int)((excl >> (10 * v)) & 1023ull);
            const int tk = take[v];
            const int ob = obase[v];
            if (xw.x == v) { if (ord < tk) trow[ob + ord] = (float)(pbase + 0); ++ord; }
            if (xw.y == v) { if (ord < tk) trow[ob + ord] = (float)(pbase + 1); ++ord; }
            if (xw.z == v) { if (ord < tk) trow[ob + ord] = (float)(pbase + 2); ++ord; }
            if (xw.w == v) { if (ord < tk) trow[ob + ord] = (float)(pbase + 3); ++ord; }
        }
    }

    // classifier (rank-0 chunk only)
    if (c == 0) {
        if (t < DD) {
            float acc = 0.0f;
            #pragma unroll
            for (int v = 0; v < VV; ++v) acc += (float)take[v] * g_arow[v][t];
            pooled[t] = acc * (1.0f / (float)KK);
        }
        __syncthreads();
        if (t < HH) {
            float acc = cb1[t];
            #pragma unroll
            for (int d = 0; d < DD; ++d) acc += pooled[d] * cw1[d * HH + t];
            h2[t] = fmaxf(acc, 0.0f);
        }
        __syncthreads();
        if (t == 0) {
            float acc = cb2[0];
            #pragma unroll
            for (int j = 0; j < HH; ++j) acc += h2[j] * cw2[j];
            out_pred[b] = 1.0f / (1.0f + expf(-acc));
        }
    }
}

extern "C" void kernel_launch(void* const* d_in, const int* in_sizes, int n_in,
                              void* d_out, int out_size) {
    const int*   x   = (const int*)  d_in[0];
    const float* emb = (const float*)d_in[1];
    const float* sw1 = (const float*)d_in[2];
    const float* sb1 = (const float*)d_in[3];
    const float* sw2 = (const float*)d_in[4];
    const float* sb2 = (const float*)d_in[5];
    const float* aw1 = (const float*)d_in[6];
    const float* ab1 = (const float*)d_in[7];
    const float* aw2 = (const float*)d_in[8];
    const float* ab2 = (const float*)d_in[9];
    const float* cw1 = (const float*)d_in[10];
    const float* cb1 = (const float*)d_in[11];
    const float* cw2 = (const float*)d_in[12];
    const float* cb2 = (const float*)d_in[13];

    float* out      = (float*)d_out;
    float* out_pred = out;
    float* out_top  = out + BB;
    float* out_sc   = out + BB + (size_t)BB * KK;

    count_kernel<<<BB * 2 + 1, TPB>>>(x, emb, sw1, sb1, sw2, sb2,
                                      aw1, ab1, aw2, ab2);
    emit_kernel<<<BB * CL, TPB>>>(x, cw1, cb1, cw2, cb2,
                                  out_pred, out_top, out_sc);
}